// round 4
// baseline (speedup 1.0000x reference)
#include <cuda_runtime.h>

// Holt double-exponential smoothing, ALPHA = BETA = 0.5.
// x: [B=32, N=2048, T=1024] float32, T contiguous. out same shape.
//
// Key trick: the recurrence is a linear state-space filter
//   (s',b') = M (s,b) + x*c,  M = [[0.5,0.5],[-0.25,0.75]],  |eig(M)| = sqrt(0.5)
// so state memory decays ~0.707^k. Split T into 4 chunks of 256; chunks 1..3
// warm-start from (0,0) 64 steps early (||M^64|| ~ 2e-10 -> below fp32 noise).
// Chunk 0 runs the exact quirky prologue (out[0]=0, out[1]=x1, scan from t=2).
// => 4x thread parallelism (262144 threads), fixing the 20% occupancy cap.

static constexpr int STEPS    = 1024;
static constexpr int VEC4     = STEPS / 4;     // 256 float4 per sequence
static constexpr int NSEQ     = 32 * 2048;     // 65536
static constexpr int CHUNKS   = 4;
static constexpr int CHUNK_V4 = VEC4 / CHUNKS; // 64 float4 = 256 steps
static constexpr int WARM_V4  = 16;            // 64 warm-up steps
static constexpr int TPB      = 256;
static constexpr int SEQ_BLKS = NSEQ / TPB;    // 256 blocks per chunk

__device__ __forceinline__ float holt_step(float& s, float& b, float xv) {
    float sn = fmaf(0.5f, s + b, 0.5f * xv);
    b = fmaf(0.5f, sn - s, 0.5f * b);
    s = sn;
    return sn;
}

__global__ __launch_bounds__(TPB)
void holt_smooth_kernel(const float* __restrict__ x, float* __restrict__ y) {
    const int chunk = blockIdx.x / SEQ_BLKS;                       // 0..3, uniform per block
    const int seq   = (blockIdx.x % SEQ_BLKS) * TPB + threadIdx.x;

    const float4* __restrict__ xin  = reinterpret_cast<const float4*>(x) + (size_t)seq * VEC4;
    float4*       __restrict__ yout = reinterpret_cast<float4*>(y)       + (size_t)seq * VEC4;

    float s, b;
    int i;  // float4 read index

    if (chunk == 0) {
        // Exact prologue: t=0..3
        float4 v = xin[0];
        float4 r;
        r.x = 0.0f;            // t=0: zero init state
        r.y = v.y;             // t=1: s = x1 (state NOT carried forward)
        s = 0.5f * v.z;        // t=2: recurrence from (s,b)=(0,0)
        b = 0.5f * s;
        r.z = s;
        r.w = holt_step(s, b, v.w);  // t=3
        yout[0] = r;
        i = 1;

        #pragma unroll 4
        for (int o = 1; o < CHUNK_V4; ++o, ++i) {
            float4 v2 = xin[i];
            float4 r2;
            r2.x = holt_step(s, b, v2.x);
            r2.y = holt_step(s, b, v2.y);
            r2.z = holt_step(s, b, v2.z);
            r2.w = holt_step(s, b, v2.w);
            yout[o] = r2;
        }
    } else {
        // Warm-up: 64 steps starting at t = chunk*256 - 64 from (0,0).
        s = 0.0f; b = 0.0f;
        i = chunk * CHUNK_V4 - WARM_V4;
        const int iend = chunk * CHUNK_V4;

        #pragma unroll 4
        for (; i < iend; ++i) {
            float4 v = xin[i];
            holt_step(s, b, v.x);
            holt_step(s, b, v.y);
            holt_step(s, b, v.z);
            holt_step(s, b, v.w);
        }

        const int obeg = chunk * CHUNK_V4;
        #pragma unroll 4
        for (int o = obeg; o < obeg + CHUNK_V4; ++o, ++i) {
            float4 v = xin[i];
            float4 r;
            r.x = holt_step(s, b, v.x);
            r.y = holt_step(s, b, v.y);
            r.z = holt_step(s, b, v.z);
            r.w = holt_step(s, b, v.w);
            yout[o] = r;
        }
    }
}

extern "C" void kernel_launch(void* const* d_in, const int* in_sizes, int n_in,
                              void* d_out, int out_size) {
    (void)in_sizes; (void)n_in; (void)out_size;
    const float* x = (const float*)d_in[0];
    float*       y = (float*)d_out;
    holt_smooth_kernel<<<CHUNKS * SEQ_BLKS, TPB>>>(x, y);
}

// round 6
// speedup vs baseline: 2.8576x; 2.8576x over previous
#include <cuda_runtime.h>

// Holt double-exponential smoothing, ALPHA = BETA = 0.5.
// x: [B=32, N=2048, T=1024] f32, T contiguous.
//
// Linear recurrence: state=(s,b), state' = M*state + c*x with
//   M = [[0.5,0.5],[-0.25,0.75]], c = (0.5, 0.25).
// Quirky init (out[0]=0, out[1]=x1, scan from t=2 with (0,0)) is equivalent
// to zeroing x[0],x[1], running the uniform recurrence from (0,0) at t=0,
// and patching out[1]=x1 (state stays (0,0) through zeroed inputs).
//
// One WARP per sequence: lanes hold consecutive float4 timestep groups
// (fully coalesced 512B warp transactions — fixes the 32-wavefront/instr
// L1tex amplification of the thread-per-sequence layout). The serial chain
// is resolved by a Kogge-Stone scan over affine offsets with PRECOMPUTED
// constant matrix powers M^4..M^64 (2 shuffles + 4 FMA per step). Exact.
// All 8 tile loads are front-batched for MLP=8 before the serial scan chain.

static constexpr int STEPS = 1024;
static constexpr int VEC4  = STEPS / 4;   // 256 float4 per sequence
static constexpr int NSEQ  = 32 * 2048;   // 65536 sequences = 65536 warps
static constexpr int TPB   = 256;         // 8 warps/block
static constexpr int WPB   = TPB / 32;
static constexpr int ITERS = VEC4 / 32;   // 8 iterations of 128 timesteps

// ---- compile-time 2x2 matrix powers (exact dyadic rationals in double) ----
struct M22 { double a, b, c, d; };
constexpr M22 mmul(M22 p, M22 q) {
    return { p.a*q.a + p.b*q.c, p.a*q.b + p.b*q.d,
             p.c*q.a + p.d*q.c, p.c*q.b + p.d*q.d };
}
constexpr M22 Mm1  {0.5, 0.5, -0.25, 0.75};
constexpr M22 Mm2  = mmul(Mm1,  Mm1);
constexpr M22 Mm4  = mmul(Mm2,  Mm2);
constexpr M22 Mm8  = mmul(Mm4,  Mm4);
constexpr M22 Mm16 = mmul(Mm8,  Mm8);
constexpr M22 Mm32 = mmul(Mm16, Mm16);
constexpr M22 Mm64 = mmul(Mm32, Mm32);

// M^k * c coefficients for the local 4-step fold:
//   state_out = M^4*state_in + M^3c*x0 + M^2c*x1 + Mc*x2 + c*x3
#define C_S    0.5f
#define C_B    0.25f
#define M1C_S  0.375f
#define M1C_B  0.0625f
#define M2C_S  0.21875f
#define M2C_B  (-0.046875f)
#define M3C_S  0.0859375f
#define M3C_B  (-0.08984375f)

__device__ __forceinline__ float holt_step(float& s, float& b, float xv) {
    float sn = fmaf(0.5f, s + b, 0.5f * xv);
    b = fmaf(0.5f, sn - s, 0.5f * b);
    s = sn;
    return sn;
}

// one Kogge-Stone scan step with constant matrix P = M^(4k)
#define SCAN_STEP(K, P)                                                     \
    {                                                                       \
        float ps = __shfl_up_sync(0xFFFFFFFFu, es, (K));                    \
        float pb = __shfl_up_sync(0xFFFFFFFFu, eb, (K));                    \
        if (lane >= (K)) {                                                  \
            es = fmaf((float)(P).a, ps, fmaf((float)(P).b, pb, es));        \
            eb = fmaf((float)(P).c, ps, fmaf((float)(P).d, pb, eb));        \
        }                                                                   \
    }

__global__ __launch_bounds__(TPB)
void holt_scan_kernel(const float* __restrict__ x, float* __restrict__ y) {
    const int lane = threadIdx.x & 31;
    const int seq  = blockIdx.x * WPB + (threadIdx.x >> 5);

    const float4* __restrict__ xin  = reinterpret_cast<const float4*>(x) + (size_t)seq * VEC4;
    float4*       __restrict__ yout = reinterpret_cast<float4*>(y)       + (size_t)seq * VEC4;

    // Front-batch all 8 tile loads: independent addresses -> MLP=8.
    float4 v[ITERS];
    #pragma unroll
    for (int it = 0; it < ITERS; ++it)
        v[it] = xin[it * 32 + lane];                  // coalesced 512B warp loads

    float cs = 0.0f, cb = 0.0f;   // carry state across 128-step iterations

    #pragma unroll
    for (int it = 0; it < ITERS; ++it) {
        float4 w = v[it];

        float patch = w.y;                            // original x[1] (lane0/it0)
        if (it == 0 && lane == 0) { w.x = 0.0f; w.y = 0.0f; }

        // local affine offset for this lane's 4 steps
        float es = fmaf(M3C_S, w.x, fmaf(M2C_S, w.y, fmaf(M1C_S, w.z, C_S * w.w)));
        float eb = fmaf(M3C_B, w.x, fmaf(M2C_B, w.y, fmaf(M1C_B, w.z, C_B * w.w)));

        // fold iteration carry into lane 0: e0 = M^4 * carry + d0
        if (lane == 0) {
            es = fmaf((float)Mm4.a, cs, fmaf((float)Mm4.b, cb, es));
            eb = fmaf((float)Mm4.c, cs, fmaf((float)Mm4.d, cb, eb));
        }

        // inclusive scan: lane l ends with state AFTER its 4 steps
        SCAN_STEP(1,  Mm4)
        SCAN_STEP(2,  Mm8)
        SCAN_STEP(4,  Mm16)
        SCAN_STEP(8,  Mm32)
        SCAN_STEP(16, Mm64)

        // exclusive prefix = state at the START of this lane's 4 steps
        float ss = __shfl_up_sync(0xFFFFFFFFu, es, 1);
        float sb = __shfl_up_sync(0xFFFFFFFFu, eb, 1);
        if (lane == 0) { ss = cs; sb = cb; }

        // next carry = lane 31's inclusive state
        cs = __shfl_sync(0xFFFFFFFFu, es, 31);
        cb = __shfl_sync(0xFFFFFFFFu, eb, 31);

        // serial replay of the 4 steps to produce outputs
        float4 o;
        o.x = holt_step(ss, sb, w.x);
        o.y = holt_step(ss, sb, w.y);
        o.z = holt_step(ss, sb, w.z);
        o.w = holt_step(ss, sb, w.w);

        if (it == 0 && lane == 0) { o.x = 0.0f; o.y = patch; }  // t=0, t=1 quirks

        yout[it * 32 + lane] = o;                     // coalesced 512B warp store
    }
}

extern "C" void kernel_launch(void* const* d_in, const int* in_sizes, int n_in,
                              void* d_out, int out_size) {
    (void)in_sizes; (void)n_in; (void)out_size;
    const float* x = (const float*)d_in[0];
    float*       y = (float*)d_out;
    holt_scan_kernel<<<NSEQ / WPB, TPB>>>(x, y);
}

// round 9
// speedup vs baseline: 2.9040x; 1.0163x over previous
#include <cuda_runtime.h>

// Holt double-exponential smoothing, ALPHA = BETA = 0.5.
// x: [B=32, N=2048, T=1024] f32, T contiguous.
//
// Linear recurrence: state=(s,b), state' = M*state + c*x with
//   M = [[0.5,0.5],[-0.25,0.75]], c = (0.5, 0.25).
// Quirky init (out[0]=0, out[1]=x1, scan from t=2 with (0,0)) == zero
// x[0],x[1], run the uniform recurrence from (0,0), patch out[1]=x1.
//
// One WARP per sequence, lanes hold consecutive float4 groups -> fully
// coalesced 512B transactions (R6 structure). Kogge-Stone scan over affine
// offsets with constexpr matrix powers.
//
// R8: decay truncation. |eig(M)| = 0.707, so M^32 ~ 1.5e-5, M^64 ~ 2e-10.
// The K=8 (M^32) and K=16 (M^64) scan steps contribute below 3e-5 relative
// (tolerance 1e-3) -> dropped. Scan: 5 steps -> 3, shuffles 14 -> 10/iter.
// Streaming loads/stores (__ldcs/__stcs): single-use data, evict-first.

static constexpr int STEPS = 1024;
static constexpr int VEC4  = STEPS / 4;   // 256 float4 per sequence
static constexpr int NSEQ  = 32 * 2048;   // 65536 sequences = 65536 warps
static constexpr int TPB   = 256;         // 8 warps/block
static constexpr int WPB   = TPB / 32;
static constexpr int ITERS = VEC4 / 32;   // 8 iterations of 128 timesteps

// ---- compile-time 2x2 matrix powers (exact dyadic rationals in double) ----
struct M22 { double a, b, c, d; };
constexpr M22 mmul(M22 p, M22 q) {
    return { p.a*q.a + p.b*q.c, p.a*q.b + p.b*q.d,
             p.c*q.a + p.d*q.c, p.c*q.b + p.d*q.d };
}
constexpr M22 Mm1  {0.5, 0.5, -0.25, 0.75};
constexpr M22 Mm2  = mmul(Mm1,  Mm1);
constexpr M22 Mm4  = mmul(Mm2,  Mm2);
constexpr M22 Mm8  = mmul(Mm4,  Mm4);
constexpr M22 Mm16 = mmul(Mm8,  Mm8);

// M^k * c coefficients for the local 4-step fold:
//   state_out = M^4*state_in + M^3c*x0 + M^2c*x1 + Mc*x2 + c*x3
#define C_S    0.5f
#define C_B    0.25f
#define M1C_S  0.375f
#define M1C_B  0.0625f
#define M2C_S  0.21875f
#define M2C_B  (-0.046875f)
#define M3C_S  0.0859375f
#define M3C_B  (-0.08984375f)

__device__ __forceinline__ float holt_step(float& s, float& b, float xv) {
    float sn = fmaf(0.5f, s + b, 0.5f * xv);
    b = fmaf(0.5f, sn - s, 0.5f * b);
    s = sn;
    return sn;
}

// one Kogge-Stone scan step with constant matrix P = M^(4k)
#define SCAN_STEP(K, P)                                                     \
    {                                                                       \
        float ps = __shfl_up_sync(0xFFFFFFFFu, es, (K));                    \
        float pb = __shfl_up_sync(0xFFFFFFFFu, eb, (K));                    \
        if (lane >= (K)) {                                                  \
            es = fmaf((float)(P).a, ps, fmaf((float)(P).b, pb, es));        \
            eb = fmaf((float)(P).c, ps, fmaf((float)(P).d, pb, eb));        \
        }                                                                   \
    }

__global__ __launch_bounds__(TPB)
void holt_scan_kernel(const float* __restrict__ x, float* __restrict__ y) {
    const int lane = threadIdx.x & 31;
    const int seq  = blockIdx.x * WPB + (threadIdx.x >> 5);

    const float4* __restrict__ xin  = reinterpret_cast<const float4*>(x) + (size_t)seq * VEC4;
    float4*       __restrict__ yout = reinterpret_cast<float4*>(y)       + (size_t)seq * VEC4;

    // Front-batch all 8 tile loads: independent addresses -> MLP=8.
    // Streaming (.cs): every line is read exactly once chip-wide.
    float4 v[ITERS];
    #pragma unroll
    for (int it = 0; it < ITERS; ++it)
        v[it] = __ldcs(&xin[it * 32 + lane]);          // coalesced 512B warp loads

    float cs = 0.0f, cb = 0.0f;   // carry state across 128-step iterations

    #pragma unroll
    for (int it = 0; it < ITERS; ++it) {
        float4 w = v[it];

        float patch = w.y;                             // original x[1] (lane0/it0)
        if (it == 0 && lane == 0) { w.x = 0.0f; w.y = 0.0f; }

        // local affine offset for this lane's 4 steps
        float es = fmaf(M3C_S, w.x, fmaf(M2C_S, w.y, fmaf(M1C_S, w.z, C_S * w.w)));
        float eb = fmaf(M3C_B, w.x, fmaf(M2C_B, w.y, fmaf(M1C_B, w.z, C_B * w.w)));

        // fold iteration carry into lane 0: e0 = M^4 * carry + d0
        if (lane == 0) {
            es = fmaf((float)Mm4.a, cs, fmaf((float)Mm4.b, cb, es));
            eb = fmaf((float)Mm4.c, cs, fmaf((float)Mm4.d, cb, eb));
        }

        // truncated inclusive scan: steps K=8 (M^32, ~1.5e-5) and K=16
        // (M^64, ~2e-10) dropped — below fp32 noise vs 1e-3 tolerance.
        SCAN_STEP(1, Mm4)
        SCAN_STEP(2, Mm8)
        SCAN_STEP(4, Mm16)

        // exclusive prefix = state at the START of this lane's 4 steps
        float ss = __shfl_up_sync(0xFFFFFFFFu, es, 1);
        float sb = __shfl_up_sync(0xFFFFFFFFu, eb, 1);
        if (lane == 0) { ss = cs; sb = cb; }

        // next carry = lane 31's inclusive state
        cs = __shfl_sync(0xFFFFFFFFu, es, 31);
        cb = __shfl_sync(0xFFFFFFFFu, eb, 31);

        // serial replay of the 4 steps to produce outputs
        float4 o;
        o.x = holt_step(ss, sb, w.x);
        o.y = holt_step(ss, sb, w.y);
        o.z = holt_step(ss, sb, w.z);
        o.w = holt_step(ss, sb, w.w);

        if (it == 0 && lane == 0) { o.x = 0.0f; o.y = patch; }  // t=0, t=1 quirks

        __stcs(&yout[it * 32 + lane], o);              // coalesced streaming store
    }
}

extern "C" void kernel_launch(void* const* d_in, const int* in_sizes, int n_in,
                              void* d_out, int out_size) {
    (void)in_sizes; (void)n_in; (void)out_size;
    const float* x = (const float*)d_in[0];
    float*       y = (float*)d_out;
    holt_scan_kernel<<<NSEQ / WPB, TPB>>>(x, y);
}